// round 14
// baseline (speedup 1.0000x reference)
#include <cuda_runtime.h>
#include <math.h>
#include <stdint.h>

#define BB 2048
#define CC 3
#define TT 300
#define JJ 25
#define TJ (TT * JJ)            // 7500 floats = 30000 B per slice
#define NSLICE (BB * CC)        // 6144
#define NBLK 296                // exactly 2 blocks per SM, one wave
#define NTHREADS 256
#define WPB 8
#define GROUPS 75               // float4-groups (25 float4 = 400 B) per slice
#define SUBS 3                  // chunks per slice
#define GPC 25                  // groups per chunk
#define CHUNK_BYTES 10000       // 25 groups * 400 B (16B aligned)
#define SLOT_BYTES (2 * CHUNK_BYTES)
#define NSLOT 4
#define DYN_SMEM (NSLOT * SLOT_BYTES)   // 80000 B
#define BASE_SL 20              // 6144 = 296*20 + 224
#define EXTRA_BLKS (NSLICE - NBLK * BASE_SL)   // 224 blocks get 21 slices

// Global accumulators (allocation-free scratch). Zero-initialized at load;
// last finishing block resets them -> deterministic across graph replays.
__device__ double g_rec = 0.0;
__device__ double g_smooth = 0.0;
__device__ unsigned int g_count = 0u;

// ---- PTX helpers -----------------------------------------------------------
__device__ __forceinline__ uint32_t smem_u32(const void* p) {
    return (uint32_t)__cvta_generic_to_shared(p);
}
__device__ __forceinline__ void mbar_init(uint32_t mbar, uint32_t cnt) {
    asm volatile("mbarrier.init.shared.b64 [%0], %1;" :: "r"(mbar), "r"(cnt) : "memory");
}
__device__ __forceinline__ void mbar_inval(uint32_t mbar) {
    asm volatile("mbarrier.inval.shared.b64 [%0];" :: "r"(mbar) : "memory");
}
__device__ __forceinline__ void mbar_expect_tx(uint32_t mbar, uint32_t bytes) {
    asm volatile("mbarrier.arrive.expect_tx.shared.b64 _, [%0], %1;"
                 :: "r"(mbar), "r"(bytes) : "memory");
}
__device__ __forceinline__ void mbar_arrive(uint32_t mbar) {
    asm volatile("mbarrier.arrive.shared.b64 _, [%0];" :: "r"(mbar) : "memory");
}
__device__ __forceinline__ void bulk_g2s(uint32_t dst, const void* src,
                                         uint32_t bytes, uint32_t mbar) {
    asm volatile(
        "cp.async.bulk.shared::cluster.global.mbarrier::complete_tx::bytes "
        "[%0], [%1], %2, [%3];"
        :: "r"(dst), "l"(src), "r"(bytes), "r"(mbar) : "memory");
}
__device__ __forceinline__ void mbar_wait(uint32_t mbar, uint32_t phase) {
    asm volatile(
        "{\n\t.reg .pred P;\n\t"
        "WAIT_%=:\n\t"
        "mbarrier.try_wait.parity.acquire.cta.shared::cta.b64 P, [%0], %1, 0x989680;\n\t"
        "@P bra.uni DONE_%=;\n\t"
        "bra.uni WAIT_%=;\n\t"
        "DONE_%=:\n\t}"
        :: "r"(mbar), "r"(phase) : "memory");
}
__device__ __forceinline__ void fence_proxy_async_cta() {
    asm volatile("fence.proxy.async.shared::cta;" ::: "memory");
}

// Element (lane,kk) of any group k: j = (4*lane+kk) % 25 -- k-invariant.
// Interior contribution to (sx - st): d - d*(x+t), d = x-t.
// FIRST (k==0, 4l+kk<25 are t==0): only +d.
// LAST  (k==74, 4l+kk>=75 are t==299): only -d*(x+t).
template <bool FIRST, bool LAST>
__device__ __forceinline__ void process4(float4 xv, float4 tv, int fourl,
                                         float acc[4], float& rec) {
    const float xa[4] = {xv.x, xv.y, xv.z, xv.w};
    const float ta[4] = {tv.x, tv.y, tv.z, tv.w};
    #pragma unroll
    for (int kk = 0; kk < 4; kk++) {
        const float d  = xa[kk] - ta[kk];
        rec = fmaf(d, d, rec);
        const float xt = xa[kk] + ta[kk];
        float c;
        if (FIRST) {
            c = d;
            if (fourl + kk >= 25) c = fmaf(-d, xt, c);
        } else if (LAST) {
            c = (fourl + kk < 75) ? d : 0.0f;
            c = fmaf(-d, xt, c);
        } else {
            c = fmaf(-d, xt, d);
        }
        acc[kk] += c;
    }
}

__device__ __forceinline__ void consume_group(const float4* __restrict__ xb,
                                              const float4* __restrict__ tb,
                                              int g, int sub, bool active,
                                              int fourl, int lane,
                                              float acc[4], float& rec) {
    const float4 z4 = {0.0f, 0.0f, 0.0f, 0.0f};
    float4 xv = z4, tv = z4;
    if (active) { xv = xb[g * JJ + lane]; tv = tb[g * JJ + lane]; }
    const int k = sub * GPC + g;
    if (k == 0)                process4<true, false>(xv, tv, fourl, acc, rec);
    else if (k == GROUPS - 1)  process4<false, true>(xv, tv, fourl, acc, rec);
    else                       process4<false, false>(xv, tv, fourl, acc, rec);
}

extern __shared__ __align__(16) char dyn[];

__global__ void __launch_bounds__(NTHREADS)
loss_kernel(const float* __restrict__ x, const float* __restrict__ tg,
            float* __restrict__ out) {
    const int tid  = threadIdx.x;
    const int warp = tid >> 5;
    const int lane = tid & 31;
    const int b    = blockIdx.x;

    const int nsl  = BASE_SL + (b < EXTRA_BLKS ? 1 : 0);   // slices this block
    const int totc = nsl * SUBS;                            // chunks this block

    __shared__ __align__(8) uint64_t m_full_st[NSLOT], m_empty_st[NSLOT];
    __shared__ float  sj[2][JJ];        // per-joint sums, slice-parity buffered
    __shared__ double s_red[WPB];

    uint32_t m_full[NSLOT], m_empty[NSLOT];
    #pragma unroll
    for (int s = 0; s < NSLOT; s++) {
        m_full[s]  = smem_u32(&m_full_st[s]);
        m_empty[s] = smem_u32(&m_empty_st[s]);
    }

    if (tid == 0) {
        #pragma unroll
        for (int s = 0; s < NSLOT; s++) {
            mbar_init(m_full[s], 1);
            mbar_init(m_empty[s], WPB);
        }
        fence_proxy_async_cta();
    }
    if (tid < 2 * JJ) ((float*)sj)[tid] = 0.0f;
    __syncthreads();

    const char* __restrict__ xbase = (const char*)x;
    const char* __restrict__ tbase = (const char*)tg;

    // Prologue: issue chunks 0..3 (all epoch 0 -> no empty wait).
    if (tid == 0) {
        #pragma unroll
        for (int c = 0; c < NSLOT; c++) {
            const int sl  = c / SUBS, sub = c - sl * SUBS;
            const size_t off = (size_t)(b + sl * NBLK) * 30000 + (size_t)sub * CHUNK_BYTES;
            const uint32_t dst = smem_u32(dyn + (c & 3) * SLOT_BYTES);
            mbar_expect_tx(m_full[c & 3], SLOT_BYTES);
            bulk_g2s(dst, xbase + off, CHUNK_BYTES, m_full[c & 3]);
            bulk_g2s(dst + CHUNK_BYTES, tbase + off, CHUNK_BYTES, m_full[c & 3]);
        }
    }

    const bool active = (lane < JJ);
    const int fourl = lane * 4;
    float acc[4] = {0.0f, 0.0f, 0.0f, 0.0f};
    float rec = 0.0f;
    double rec_d = 0.0, smooth_d = 0.0;

    for (int c = 0; c < totc; c++) {
        const int slot = c & 3;
        mbar_wait(m_full[slot], (c >> 2) & 1);

        const float4* xb = (const float4*)(dyn + slot * SLOT_BYTES);
        const float4* tb = (const float4*)(dyn + slot * SLOT_BYTES + CHUNK_BYTES);
        const int sl  = c / SUBS;
        const int sub = c - sl * SUBS;

        for (int g = warp; g < 24; g += WPB)
            consume_group(xb, tb, g, sub, active, fourl, lane, acc, rec);
        if (warp == WPB - 1)
            consume_group(xb, tb, 24, sub, active, fourl, lane, acc, rec);

        __syncwarp();
        if (lane == 0) mbar_arrive(m_empty[slot]);

        // Producer: refill this ring position for chunk c+4.
        if (tid == 0) {
            const int cn = c + NSLOT;
            if (cn < totc) {
                const int en = cn >> 2;
                mbar_wait(m_empty[cn & 3], (en - 1) & 1);
                const int sl2  = cn / SUBS, sub2 = cn - sl2 * SUBS;
                const size_t off = (size_t)(b + sl2 * NBLK) * 30000 + (size_t)sub2 * CHUNK_BYTES;
                const uint32_t dst = smem_u32(dyn + (cn & 3) * SLOT_BYTES);
                mbar_expect_tx(m_full[cn & 3], SLOT_BYTES);
                bulk_g2s(dst, xbase + off, CHUNK_BYTES, m_full[cn & 3]);
                bulk_g2s(dst + CHUNK_BYTES, tbase + off, CHUNK_BYTES, m_full[cn & 3]);
            }
        }

        if (sub == SUBS - 1) {
            // ---- slice boundary: merge smooth accumulators ----
            rec_d += (double)rec; rec = 0.0f;
            const int p = sl & 1;
            if (active) {
                #pragma unroll
                for (int kk = 0; kk < 4; kk++) {
                    const int v = fourl + kk;
                    const int j = (v >= 75) ? v - 75 : (v >= 50) ? v - 50
                                : (v >= 25) ? v - 25 : v;
                    atomicAdd(&sj[p][j], acc[kk]);
                    acc[kk] = 0.0f;
                }
            }
            __syncthreads();
            if (warp == 0) {
                float av = (lane < JJ - 1) ? fabsf(sj[p][lane]) : 0.0f;
                #pragma unroll
                for (int o = 16; o > 0; o >>= 1)
                    av += __shfl_xor_sync(0xffffffffu, av, o);
                if (lane == 0) smooth_d += sqrt((double)av) / (double)TJ;
            }
            if (tid < JJ) sj[p ^ 1][tid] = 0.0f;   // reset next slice's buffer
            __syncthreads();
        }
    }

    // Final block reduce of rec_d; smooth_d lives on thread 0 only.
    #pragma unroll
    for (int o = 16; o > 0; o >>= 1)
        rec_d += __shfl_xor_sync(0xffffffffu, rec_d, o);
    if (lane == 0) s_red[warp] = rec_d;
    __syncthreads();

    if (tid == 0) {
        double rtot = 0.0;
        #pragma unroll
        for (int w = 0; w < WPB; w++) rtot += s_red[w];
        #pragma unroll
        for (int s = 0; s < NSLOT; s++) { mbar_inval(m_full[s]); mbar_inval(m_empty[s]); }
        atomicAdd(&g_rec, rtot);
        atomicAdd(&g_smooth, smooth_d);
        __threadfence();
        const unsigned int ticket = atomicAdd(&g_count, 1u);
        if (ticket == NBLK - 1) {
            const double rec_sum = atomicAdd(&g_rec, 0.0);
            const double sm_sum  = atomicAdd(&g_smooth, 0.0);
            const double rec_mean    = rec_sum / ((double)BB * CC * TT * JJ);
            const double smooth_mean = sm_sum  / ((double)BB * CC);
            out[0] = (float)(2.0 * rec_mean + 3.0 * smooth_mean);
            g_rec = 0.0;
            g_smooth = 0.0;
            __threadfence();
            g_count = 0u;
        }
    }
}

extern "C" void kernel_launch(void* const* d_in, const int* in_sizes, int n_in,
                              void* d_out, int out_size) {
    const float* x  = (const float*)d_in[0];
    const float* tg = (const float*)d_in[1];
    float* out = (float*)d_out;

    cudaFuncSetAttribute(loss_kernel,
                         cudaFuncAttributeMaxDynamicSharedMemorySize, DYN_SMEM);
    loss_kernel<<<NBLK, NTHREADS, DYN_SMEM>>>(x, tg, out);
}

// round 15
// speedup vs baseline: 1.1205x; 1.1205x over previous
#include <cuda_runtime.h>
#include <math.h>

#define BB 2048
#define CC 3
#define TT 300
#define JJ 25
#define TJ (TT * JJ)            // 7500 elements per (b,c) slice
#define NSLICE (BB * CC)        // 6144 slices
#define WPB 8                   // warps per block (1 warp = 1 slice)
#define NBLK (NSLICE / WPB)     // 768 blocks
#define NTHREADS (WPB * 32)
#define NF4 (TJ / 4)            // 1875 float4 per slice
#define KMAX (NF4 / JJ)         // 75 groups of 25 float4 (= 4 frames each)

// Global accumulators (allocation-free scratch). Zero-initialized at load;
// last finishing block resets them -> deterministic across graph replays.
__device__ double g_rec = 0.0;
__device__ double g_smooth = 0.0;
__device__ unsigned int g_count = 0u;

// Element (lane,kk) in group k: j = (4*lane+kk) % 25, invariant over k.
// Interior contribution to (sx - st): d - d*(x+t), d = x-t.
// FIRST (t==0 rows, 4l+kk<25): only +d.   LAST (t==299, 4l+kk>=75): only -d*(x+t).
template <bool FIRST, bool LAST>
__device__ __forceinline__ void process4(float4 xv, float4 tv, int fourl,
                                         float acc[4], float& rec) {
    const float xa[4] = {xv.x, xv.y, xv.z, xv.w};
    const float ta[4] = {tv.x, tv.y, tv.z, tv.w};
    #pragma unroll
    for (int kk = 0; kk < 4; kk++) {
        const float d  = xa[kk] - ta[kk];
        rec = fmaf(d, d, rec);
        const float xt = xa[kk] + ta[kk];
        float c;
        if (FIRST) {
            c = d;
            if (fourl + kk >= 25) c = fmaf(-d, xt, c);
        } else if (LAST) {
            c = (fourl + kk < 75) ? d : 0.0f;
            c = fmaf(-d, xt, c);
        } else {
            c = fmaf(-d, xt, d);
        }
        acc[kk] += c;
    }
}

__global__ void __launch_bounds__(NTHREADS)
loss_kernel(const float* __restrict__ x, const float* __restrict__ tg,
            float* __restrict__ out) {
    const int warp = threadIdx.x >> 5;
    const int lane = threadIdx.x & 31;
    const int slice = blockIdx.x * WPB + warp;          // < 6144

    const float4* __restrict__ x4 = (const float4*)(x  + (size_t)slice * TJ);
    const float4* __restrict__ t4 = (const float4*)(tg + (size_t)slice * TJ);

    const bool active = (lane < JJ);
    const int fourl = lane * 4;
    // Inactive lanes read the slice base: in-bounds, broadcast, no extra lines.
    const int ld = active ? lane : 0;

    float acc[4] = {0.0f, 0.0f, 0.0f, 0.0f};
    float rec = 0.0f;
    const float4 z4 = {0.0f, 0.0f, 0.0f, 0.0f};

    // k = 0 (contains all t==0 elements)
    {
        float4 xv = __ldcs(x4 + ld);
        float4 tv = __ldcs(t4 + ld);
        if (!active) { xv = z4; tv = z4; }
        process4<true, false>(xv, tv, fourl, acc, rec);
    }
    // interior groups: t in (0, 299) for every element -> branchless.
    // Deep unroll: 8 independent LDG.128 front-batched per iteration group.
    // Occupancy is grid-limited (41.5 warps/SM) so register growth is free.
    #pragma unroll 4
    for (int k = 1; k < KMAX - 1; k++) {
        float4 xv = __ldcs(x4 + k * JJ + ld);
        float4 tv = __ldcs(t4 + k * JJ + ld);
        if (!active) { xv = z4; tv = z4; }
        process4<false, false>(xv, tv, fourl, acc, rec);
    }
    // k = 74 (contains all t==299 elements)
    {
        float4 xv = __ldcs(x4 + (KMAX - 1) * JJ + ld);
        float4 tv = __ldcs(t4 + (KMAX - 1) * JJ + ld);
        if (!active) { xv = z4; tv = z4; }
        process4<false, true>(xv, tv, fourl, acc, rec);
    }

    // rec: full-warp shuffle reduce.
    #pragma unroll
    for (int o = 16; o > 0; o >>= 1)
        rec += __shfl_xor_sync(0xffffffffu, rec, o);

    // Smooth: fold 100 (lane,kk) accumulators into per-joint sums via smem.
    __shared__ float sj[WPB][JJ];
    if (active) sj[warp][lane] = 0.0f;
    __syncwarp();
    if (active) {
        #pragma unroll
        for (int kk = 0; kk < 4; kk++) {
            const int v = fourl + kk;
            const int j = (v >= 75) ? v - 75 : (v >= 50) ? v - 50
                        : (v >= 25) ? v - 25 : v;
            atomicAdd(&sj[warp][j], acc[kk]);
        }
    }
    __syncwarp();

    float av = (lane < JJ - 1) ? fabsf(sj[warp][lane]) : 0.0f;
    #pragma unroll
    for (int o = 16; o > 0; o >>= 1)
        av += __shfl_xor_sync(0xffffffffu, av, o);

    __shared__ double s_rec[WPB];
    __shared__ double s_sm[WPB];
    if (lane == 0) {
        s_rec[warp] = (double)rec;
        s_sm[warp]  = sqrt((double)av) / (double)TJ;
    }
    __syncthreads();

    if (threadIdx.x == 0) {
        double rtot = 0.0, stot = 0.0;
        #pragma unroll
        for (int w = 0; w < WPB; w++) { rtot += s_rec[w]; stot += s_sm[w]; }
        atomicAdd(&g_rec, rtot);
        atomicAdd(&g_smooth, stot);
        __threadfence();
        const unsigned int ticket = atomicAdd(&g_count, 1u);
        if (ticket == NBLK - 1) {
            const double rec_sum = atomicAdd(&g_rec, 0.0);
            const double sm_sum  = atomicAdd(&g_smooth, 0.0);
            const double rec_mean    = rec_sum / ((double)BB * CC * TT * JJ);
            const double smooth_mean = sm_sum  / ((double)BB * CC);
            out[0] = (float)(2.0 * rec_mean + 3.0 * smooth_mean);
            g_rec = 0.0;
            g_smooth = 0.0;
            __threadfence();
            g_count = 0u;
        }
    }
}

extern "C" void kernel_launch(void* const* d_in, const int* in_sizes, int n_in,
                              void* d_out, int out_size) {
    const float* x  = (const float*)d_in[0];
    const float* tg = (const float*)d_in[1];
    float* out = (float*)d_out;

    loss_kernel<<<NBLK, NTHREADS>>>(x, tg, out);
}

// round 17
// speedup vs baseline: 1.1602x; 1.0355x over previous
#include <cuda_runtime.h>
#include <math.h>

#define BB 2048
#define CC 3
#define TT 300
#define JJ 25
#define TJ (TT * JJ)            // 7500 elements per (b,c) slice
#define NSLICE (BB * CC)        // 6144 slices
#define WPB 2                   // warps per block (1 warp = 1 slice)
#define NBLK (NSLICE / WPB)     // 3072 blocks -> 20.75/SM, 1.2% tail imbalance
#define NTHREADS (WPB * 32)
#define NF4 (TJ / 4)            // 1875 float4 per slice
#define KMAX (NF4 / JJ)         // 75 groups of 25 float4 (= 4 frames each)

// Global accumulators (allocation-free scratch). Zero-initialized at load;
// last finishing block resets them -> deterministic across graph replays.
__device__ double g_rec = 0.0;
__device__ double g_smooth = 0.0;
__device__ unsigned int g_count = 0u;

// Element (lane,kk) in group k: j = (4*lane+kk) % 25, invariant over k.
// Interior contribution to (sx - st): d - d*(x+t), d = x-t.
// FIRST (t==0 rows, 4l+kk<25): only +d.   LAST (t==299, 4l+kk>=75): only -d*(x+t).
template <bool FIRST, bool LAST>
__device__ __forceinline__ void process4(float4 xv, float4 tv, int fourl,
                                         float acc[4], float& rec) {
    const float xa[4] = {xv.x, xv.y, xv.z, xv.w};
    const float ta[4] = {tv.x, tv.y, tv.z, tv.w};
    #pragma unroll
    for (int kk = 0; kk < 4; kk++) {
        const float d  = xa[kk] - ta[kk];
        rec = fmaf(d, d, rec);
        const float xt = xa[kk] + ta[kk];
        float c;
        if (FIRST) {
            c = d;
            if (fourl + kk >= 25) c = fmaf(-d, xt, c);
        } else if (LAST) {
            c = (fourl + kk < 75) ? d : 0.0f;
            c = fmaf(-d, xt, c);
        } else {
            c = fmaf(-d, xt, d);
        }
        acc[kk] += c;
    }
}

__global__ void __launch_bounds__(NTHREADS)
loss_kernel(const float* __restrict__ x, const float* __restrict__ tg,
            float* __restrict__ out) {
    const int warp = threadIdx.x >> 5;
    const int lane = threadIdx.x & 31;
    const int slice = blockIdx.x * WPB + warp;          // < 6144

    const float4* __restrict__ x4 = (const float4*)(x  + (size_t)slice * TJ);
    const float4* __restrict__ t4 = (const float4*)(tg + (size_t)slice * TJ);

    const bool active = (lane < JJ);
    const int fourl = lane * 4;
    // Inactive lanes read the slice base: in-bounds, broadcast, no extra lines.
    const int ld = active ? lane : 0;

    float acc[4] = {0.0f, 0.0f, 0.0f, 0.0f};
    float rec = 0.0f;
    const float4 z4 = {0.0f, 0.0f, 0.0f, 0.0f};

    // k = 0 (contains all t==0 elements)
    {
        float4 xv = __ldcs(x4 + ld);
        float4 tv = __ldcs(t4 + ld);
        if (!active) { xv = z4; tv = z4; }
        process4<true, false>(xv, tv, fourl, acc, rec);
    }
    // interior groups: t in (0, 299) for every element -> branchless.
    #pragma unroll 4
    for (int k = 1; k < KMAX - 1; k++) {
        float4 xv = __ldcs(x4 + k * JJ + ld);
        float4 tv = __ldcs(t4 + k * JJ + ld);
        if (!active) { xv = z4; tv = z4; }
        process4<false, false>(xv, tv, fourl, acc, rec);
    }
    // k = 74 (contains all t==299 elements)
    {
        float4 xv = __ldcs(x4 + (KMAX - 1) * JJ + ld);
        float4 tv = __ldcs(t4 + (KMAX - 1) * JJ + ld);
        if (!active) { xv = z4; tv = z4; }
        process4<false, true>(xv, tv, fourl, acc, rec);
    }

    // rec: full-warp shuffle reduce.
    #pragma unroll
    for (int o = 16; o > 0; o >>= 1)
        rec += __shfl_xor_sync(0xffffffffu, rec, o);

    // Smooth: fold 100 (lane,kk) accumulators into per-joint sums via smem.
    __shared__ float sj[WPB][JJ];
    if (active) sj[warp][lane] = 0.0f;
    __syncwarp();
    if (active) {
        #pragma unroll
        for (int kk = 0; kk < 4; kk++) {
            const int v = fourl + kk;
            const int j = (v >= 75) ? v - 75 : (v >= 50) ? v - 50
                        : (v >= 25) ? v - 25 : v;
            atomicAdd(&sj[warp][j], acc[kk]);
        }
    }
    __syncwarp();

    float av = (lane < JJ - 1) ? fabsf(sj[warp][lane]) : 0.0f;
    #pragma unroll
    for (int o = 16; o > 0; o >>= 1)
        av += __shfl_xor_sync(0xffffffffu, av, o);

    __shared__ double s_rec[WPB];
    __shared__ double s_sm[WPB];
    if (lane == 0) {
        s_rec[warp] = (double)rec;
        s_sm[warp]  = sqrt((double)av) / (double)TJ;
    }
    __syncthreads();

    if (threadIdx.x == 0) {
        double rtot = 0.0, stot = 0.0;
        #pragma unroll
        for (int w = 0; w < WPB; w++) { rtot += s_rec[w]; stot += s_sm[w]; }
        atomicAdd(&g_rec, rtot);
        atomicAdd(&g_smooth, stot);
        __threadfence();
        const unsigned int ticket = atomicAdd(&g_count, 1u);
        if (ticket == NBLK - 1) {
            const double rec_sum = atomicAdd(&g_rec, 0.0);
            const double sm_sum  = atomicAdd(&g_smooth, 0.0);
            const double rec_mean    = rec_sum / ((double)BB * CC * TT * JJ);
            const double smooth_mean = sm_sum  / ((double)BB * CC);
            out[0] = (float)(2.0 * rec_mean + 3.0 * smooth_mean);
            g_rec = 0.0;
            g_smooth = 0.0;
            __threadfence();
            g_count = 0u;
        }
    }
}

extern "C" void kernel_launch(void* const* d_in, const int* in_sizes, int n_in,
                              void* d_out, int out_size) {
    const float* x  = (const float*)d_in[0];
    const float* tg = (const float*)d_in[1];
    float* out = (float*)d_out;

    loss_kernel<<<NBLK, NTHREADS>>>(x, tg, out);
}